// round 4
// baseline (speedup 1.0000x reference)
#include <cuda_runtime.h>

#define FULLMASK 0xFFFFFFFFu
#define WARPS_PER_ROW 8

// One 256-thread block per row; each warp owns a 1024-element chunk.
// Phase 1: single packed read of obs (32 bits/lane), block count scan -> s_start,
//          chunk D_base via lgamma closed form.
// Phase 2 (restructured for ILP): all 8 sub-iteration lane-prefixes from ballots,
//          8 independent logs, 8 INTERLEAVED warp scans, serial 8-add cross prefix,
//          8 independent exps. Store phase has no transcendental/scan dependence.
__global__ void __launch_bounds__(32 * WARPS_PER_ROW, 6)
bbm_kernel(const float* __restrict__ obs,
           const float* __restrict__ alpha1,
           const float* __restrict__ beta1,
           const float* __restrict__ alpha2,
           const float* __restrict__ beta2,
           const float* __restrict__ mixw,
           float* __restrict__ out,
           int B, int T)
{
    const int wid  = threadIdx.x >> 5;
    const int lane = threadIdx.x & 31;
    const int row  = blockIdx.x;

    const unsigned ltmask = (lane == 0) ? 0u : (FULLMASK >> (32 - lane));

    const float a1c = __ldg(alpha1 + row);
    const float b1c = __ldg(beta1  + row);
    const float a2c = __ldg(alpha2 + row);
    const float b2c = __ldg(beta2  + row);
    const float ab1 = a1c + b1c;
    const float ab2 = a2c + b2c;
    const float w   = __ldg(mixw);
    const float omw = 1.0f - w;

    const int chunk = T / WARPS_PER_ROW;   // 1024

    const float4* __restrict__ orow =
        reinterpret_cast<const float4*>(obs + (size_t)row * (size_t)T);

    const size_t NT = (size_t)B * (size_t)T;
    float* o_a1 = out + (size_t)row * (size_t)T;

    __shared__ int smem_cnt[WARPS_PER_ROW];

    // ---------- Phase 1: load chunk, pack bits (32 per lane), count ----------
    unsigned packed = 0;
    const int vbase = wid * (chunk >> 2) + lane;
    #pragma unroll
    for (int i = 0; i < 8; ++i) {
        const float4 v = orow[vbase + i * 32];
        unsigned nib = (unsigned)(v.x > 0.5f)
                     | ((unsigned)(v.y > 0.5f) << 1)
                     | ((unsigned)(v.z > 0.5f) << 2)
                     | ((unsigned)(v.w > 0.5f) << 3);
        packed |= nib << (4 * i);
    }
    const int warpcnt = __reduce_add_sync(FULLMASK, __popc(packed));
    if (lane == 0) smem_cnt[wid] = warpcnt;
    __syncthreads();

    int s_start = 0;
    #pragma unroll
    for (int k = 0; k < WARPS_PER_ROW; ++k)
        if (k < wid) s_start += smem_cnt[k];

    // ---------- chunk D_base via lgamma closed form ----------
    float Dchunk = 0.0f;
    if (wid != 0) {
        const float tf = (float)(wid * chunk);
        const float sf = (float)s_start;
        const float ff = tf - sf;
        const float d2 = (lgammaf(a2c + sf) + lgammaf(b2c + ff) - lgammaf(ab2 + tf))
                       - (lgammaf(a2c) + lgammaf(b2c) - lgammaf(ab2));
        const float d1 = (lgammaf(a1c + sf) + lgammaf(b1c + ff) - lgammaf(ab1 + tf))
                       - (lgammaf(a1c) + lgammaf(b1c) - lgammaf(ab1));
        Dchunk = d2 - d1;
    }

    // ---------- per-sub-iter per-lane s0 (all from ballots, no float dep) ----------
    unsigned s0pack[4];                // two 16-bit s0 per register
    {
        int s_run = s_start;
        #pragma unroll
        for (int i = 0; i < 8; ++i) {
            const unsigned nib = (packed >> (4 * i)) & 0xF;
            const unsigned m0 = __ballot_sync(FULLMASK, nib & 1u);
            const unsigned m1 = __ballot_sync(FULLMASK, nib & 2u);
            const unsigned m2 = __ballot_sync(FULLMASK, nib & 4u);
            const unsigned m3 = __ballot_sync(FULLMASK, nib & 8u);
            const int lp = __popc(m0 & ltmask) + __popc(m1 & ltmask)
                         + __popc(m2 & ltmask) + __popc(m3 & ltmask);
            const unsigned s0 = (unsigned)(s_run + lp);
            if (i & 1) s0pack[i >> 1] |= s0 << 16;
            else       s0pack[i >> 1]  = s0;
            s_run += __popc(m0) + __popc(m1) + __popc(m2) + __popc(m3);
        }
    }

    const int tchunk = wid * chunk;

    // ---------- 8 independent per-lane log-deltas ----------
    float finc[8];
    #pragma unroll
    for (int i = 0; i < 8; ++i) {
        const int s0 = (int)((s0pack[i >> 1] >> ((i & 1) * 16)) & 0xFFFFu);
        const unsigned nib = (packed >> (4 * i)) & 0xF;
        const float t0f = (float)(tchunk + (i << 7) + (lane << 2));
        float cn = 1.0f, cd = 1.0f;
        int ss = s0;
        #pragma unroll
        for (int j = 0; j < 4; ++j) {
            const int bj = (nib >> j) & 1;
            const float tf = t0f + (float)j;
            const float sf = (float)ss;
            const float ff = tf - sf;
            const float xv = bj ? sf  : ff;
            const float c2 = bj ? a2c : b2c;
            const float c1 = bj ? a1c : b1c;
            cn *= (c2 + xv) * (ab1 + tf);
            cd *= (c1 + xv) * (ab2 + tf);
            ss += bj;
        }
        finc[i] = __logf(__fdividef(cn, cd));
    }

    // ---------- 8 interleaved warp scans (one scan's latency) ----------
    #pragma unroll
    for (int d = 1; d < 32; d <<= 1) {
        #pragma unroll
        for (int i = 0; i < 8; ++i) {
            const float n = __shfl_up_sync(FULLMASK, finc[i], d);
            if (lane >= d) finc[i] += n;
        }
    }

    // ---------- cross-sub-iter prefix + 8 independent exps ----------
    float omwEb[8];
    {
        float Drun = Dchunk;
        #pragma unroll
        for (int i = 0; i < 8; ++i) {
            const float tot  = __shfl_sync(FULLMASK, finc[i], 31);
            float excl = __shfl_up_sync(FULLMASK, finc[i], 1);
            if (lane == 0) excl = 0.0f;
            omwEb[i] = omw * __expf(Drun + excl);
            Drun += tot;
        }
    }

    // ---------- store phase: recompute cheap factors, 1 div/element ----------
    #pragma unroll
    for (int i = 0; i < 8; ++i) {
        const int s0 = (int)((s0pack[i >> 1] >> ((i & 1) * 16)) & 0xFFFFu);
        const unsigned nib = (packed >> (4 * i)) & 0xF;
        const int   t0  = tchunk + (i << 7) + (lane << 2);
        const float t0f = (float)t0;
        const float eb  = omwEb[i];

        float cn = 1.0f, cd = 1.0f;
        float oa1[4], ob1[4], oa2[4], ob2[4], opm[4];
        int ss = s0;
        #pragma unroll
        for (int j = 0; j < 4; ++j) {
            const int bj = (nib >> j) & 1;
            const float tf = t0f + (float)j;
            const float sf = (float)ss;
            const float ff = tf - sf;
            oa1[j] = a1c + sf;
            ob1[j] = b1c + ff;
            oa2[j] = a2c + sf;
            ob2[j] = b2c + ff;
            const float wn = w * cd;
            opm[j] = __fdividef(wn, fmaf(eb, cn, wn));
            const float xv = bj ? sf  : ff;
            const float c2 = bj ? a2c : b2c;
            const float c1 = bj ? a1c : b1c;
            cn *= (c2 + xv) * (ab1 + tf);
            cd *= (c1 + xv) * (ab2 + tf);
            ss += bj;
        }

        float* p = o_a1 + t0;
        *reinterpret_cast<float4*>(p)          = make_float4(oa1[0], oa1[1], oa1[2], oa1[3]);
        *reinterpret_cast<float4*>(p + NT)     = make_float4(ob1[0], ob1[1], ob1[2], ob1[3]);
        *reinterpret_cast<float4*>(p + 2 * NT) = make_float4(oa2[0], oa2[1], oa2[2], oa2[3]);
        *reinterpret_cast<float4*>(p + 3 * NT) = make_float4(ob2[0], ob2[1], ob2[2], ob2[3]);
        *reinterpret_cast<float4*>(p + 4 * NT) = make_float4(opm[0], opm[1], opm[2], opm[3]);
    }
}

extern "C" void kernel_launch(void* const* d_in, const int* in_sizes, int n_in,
                              void* d_out, int out_size)
{
    const float* obs = (const float*)d_in[0];
    const float* a1  = (const float*)d_in[1];
    const float* b1  = (const float*)d_in[2];
    const float* a2  = (const float*)d_in[3];
    const float* b2  = (const float*)d_in[4];
    const float* mw  = (const float*)d_in[5];

    const int B = in_sizes[1];
    const int T = in_sizes[0] / B;

    dim3 block(32 * WARPS_PER_ROW);
    dim3 grid(B);
    bbm_kernel<<<grid, block>>>(obs, a1, b1, a2, b2, mw, (float*)d_out, B, T);
}

// round 5
// speedup vs baseline: 1.4132x; 1.4132x over previous
#include <cuda_runtime.h>

#define FULLMASK 0xFFFFFFFFu
#define WARPS_PER_ROW 8

// One 256-thread block per row; each warp owns a 1024-element chunk.
// Phase 1: single packed read of obs (32 bits/lane), block count scan -> s_start,
//          chunk D_base via lgamma closed form.
// Phase 2: all 8 sub-iteration lane-prefixes from ballots, 8 independent logs,
//          8 INTERLEAVED warp scans, serial 8-add cross prefix, 8 independent exps.
// NO register cap: spill-free (R4 post-mortem: forced 40 regs cost ~1GB spill traffic).
__global__ void __launch_bounds__(32 * WARPS_PER_ROW)
bbm_kernel(const float* __restrict__ obs,
           const float* __restrict__ alpha1,
           const float* __restrict__ beta1,
           const float* __restrict__ alpha2,
           const float* __restrict__ beta2,
           const float* __restrict__ mixw,
           float* __restrict__ out,
           int B, int T)
{
    const int wid  = threadIdx.x >> 5;
    const int lane = threadIdx.x & 31;
    const int row  = blockIdx.x;

    const unsigned ltmask = (lane == 0) ? 0u : (FULLMASK >> (32 - lane));

    const float a1c = __ldg(alpha1 + row);
    const float b1c = __ldg(beta1  + row);
    const float a2c = __ldg(alpha2 + row);
    const float b2c = __ldg(beta2  + row);
    const float ab1 = a1c + b1c;
    const float ab2 = a2c + b2c;
    const float w   = __ldg(mixw);
    const float omw = 1.0f - w;

    const int chunk = T / WARPS_PER_ROW;   // 1024

    const float4* __restrict__ orow =
        reinterpret_cast<const float4*>(obs + (size_t)row * (size_t)T);

    const size_t NT = (size_t)B * (size_t)T;
    float* o_a1 = out + (size_t)row * (size_t)T;

    __shared__ int smem_cnt[WARPS_PER_ROW];

    // ---------- Phase 1: load chunk, pack bits (32 per lane), count ----------
    unsigned packed = 0;
    const int vbase = wid * (chunk >> 2) + lane;
    #pragma unroll
    for (int i = 0; i < 8; ++i) {
        const float4 v = orow[vbase + i * 32];
        unsigned nib = (unsigned)(v.x > 0.5f)
                     | ((unsigned)(v.y > 0.5f) << 1)
                     | ((unsigned)(v.z > 0.5f) << 2)
                     | ((unsigned)(v.w > 0.5f) << 3);
        packed |= nib << (4 * i);
    }
    const int warpcnt = __reduce_add_sync(FULLMASK, __popc(packed));
    if (lane == 0) smem_cnt[wid] = warpcnt;
    __syncthreads();

    int s_start = 0;
    #pragma unroll
    for (int k = 0; k < WARPS_PER_ROW; ++k)
        if (k < wid) s_start += smem_cnt[k];

    // ---------- chunk D_base via lgamma closed form ----------
    float Dchunk = 0.0f;
    if (wid != 0) {
        const float tf = (float)(wid * chunk);
        const float sf = (float)s_start;
        const float ff = tf - sf;
        const float d2 = (lgammaf(a2c + sf) + lgammaf(b2c + ff) - lgammaf(ab2 + tf))
                       - (lgammaf(a2c) + lgammaf(b2c) - lgammaf(ab2));
        const float d1 = (lgammaf(a1c + sf) + lgammaf(b1c + ff) - lgammaf(ab1 + tf))
                       - (lgammaf(a1c) + lgammaf(b1c) - lgammaf(ab1));
        Dchunk = d2 - d1;
    }

    // ---------- per-sub-iter per-lane s0 (all from ballots, int only) ----------
    unsigned s0pack[4];                // two 16-bit s0 per register
    {
        int s_run = s_start;
        #pragma unroll
        for (int i = 0; i < 8; ++i) {
            const unsigned nib = (packed >> (4 * i)) & 0xF;
            const unsigned m0 = __ballot_sync(FULLMASK, nib & 1u);
            const unsigned m1 = __ballot_sync(FULLMASK, nib & 2u);
            const unsigned m2 = __ballot_sync(FULLMASK, nib & 4u);
            const unsigned m3 = __ballot_sync(FULLMASK, nib & 8u);
            const int lp = __popc(m0 & ltmask) + __popc(m1 & ltmask)
                         + __popc(m2 & ltmask) + __popc(m3 & ltmask);
            const unsigned s0 = (unsigned)(s_run + lp);
            if (i & 1) s0pack[i >> 1] |= s0 << 16;
            else       s0pack[i >> 1]  = s0;
            s_run += __popc(m0) + __popc(m1) + __popc(m2) + __popc(m3);
        }
    }

    const int tchunk = wid * chunk;

    // ---------- 8 independent per-lane log-deltas ----------
    float finc[8];
    #pragma unroll
    for (int i = 0; i < 8; ++i) {
        const int s0 = (int)((s0pack[i >> 1] >> ((i & 1) * 16)) & 0xFFFFu);
        const unsigned nib = (packed >> (4 * i)) & 0xF;
        const float t0f = (float)(tchunk + (i << 7) + (lane << 2));
        float cn = 1.0f, cd = 1.0f;
        int ss = s0;
        #pragma unroll
        for (int j = 0; j < 4; ++j) {
            const int bj = (nib >> j) & 1;
            const float tf = t0f + (float)j;
            const float sf = (float)ss;
            const float ff = tf - sf;
            const float xv = bj ? sf  : ff;
            const float c2 = bj ? a2c : b2c;
            const float c1 = bj ? a1c : b1c;
            cn *= (c2 + xv) * (ab1 + tf);
            cd *= (c1 + xv) * (ab2 + tf);
            ss += bj;
        }
        finc[i] = __logf(__fdividef(cn, cd));
    }

    // ---------- 8 interleaved warp scans (one scan's latency) ----------
    #pragma unroll
    for (int d = 1; d < 32; d <<= 1) {
        #pragma unroll
        for (int i = 0; i < 8; ++i) {
            const float n = __shfl_up_sync(FULLMASK, finc[i], d);
            if (lane >= d) finc[i] += n;
        }
    }

    // ---------- cross-sub-iter prefix + 8 independent exps ----------
    float omwEb[8];
    {
        float Drun = Dchunk;
        #pragma unroll
        for (int i = 0; i < 8; ++i) {
            const float tot  = __shfl_sync(FULLMASK, finc[i], 31);
            float excl = __shfl_up_sync(FULLMASK, finc[i], 1);
            if (lane == 0) excl = 0.0f;
            omwEb[i] = omw * __expf(Drun + excl);
            Drun += tot;
        }
    }

    // ---------- store phase: recompute cheap factors, 1 div/element ----------
    #pragma unroll
    for (int i = 0; i < 8; ++i) {
        const int s0 = (int)((s0pack[i >> 1] >> ((i & 1) * 16)) & 0xFFFFu);
        const unsigned nib = (packed >> (4 * i)) & 0xF;
        const int   t0  = tchunk + (i << 7) + (lane << 2);
        const float t0f = (float)t0;
        const float eb  = omwEb[i];

        float cn = 1.0f, cd = 1.0f;
        float oa1[4], ob1[4], oa2[4], ob2[4], opm[4];
        int ss = s0;
        #pragma unroll
        for (int j = 0; j < 4; ++j) {
            const int bj = (nib >> j) & 1;
            const float tf = t0f + (float)j;
            const float sf = (float)ss;
            const float ff = tf - sf;
            oa1[j] = a1c + sf;
            ob1[j] = b1c + ff;
            oa2[j] = a2c + sf;
            ob2[j] = b2c + ff;
            const float wn = w * cd;
            opm[j] = __fdividef(wn, fmaf(eb, cn, wn));
            const float xv = bj ? sf  : ff;
            const float c2 = bj ? a2c : b2c;
            const float c1 = bj ? a1c : b1c;
            cn *= (c2 + xv) * (ab1 + tf);
            cd *= (c1 + xv) * (ab2 + tf);
            ss += bj;
        }

        float* p = o_a1 + t0;
        *reinterpret_cast<float4*>(p)          = make_float4(oa1[0], oa1[1], oa1[2], oa1[3]);
        *reinterpret_cast<float4*>(p + NT)     = make_float4(ob1[0], ob1[1], ob1[2], ob1[3]);
        *reinterpret_cast<float4*>(p + 2 * NT) = make_float4(oa2[0], oa2[1], oa2[2], oa2[3]);
        *reinterpret_cast<float4*>(p + 3 * NT) = make_float4(ob2[0], ob2[1], ob2[2], ob2[3]);
        *reinterpret_cast<float4*>(p + 4 * NT) = make_float4(opm[0], opm[1], opm[2], opm[3]);
    }
}

extern "C" void kernel_launch(void* const* d_in, const int* in_sizes, int n_in,
                              void* d_out, int out_size)
{
    const float* obs = (const float*)d_in[0];
    const float* a1  = (const float*)d_in[1];
    const float* b1  = (const float*)d_in[2];
    const float* a2  = (const float*)d_in[3];
    const float* b2  = (const float*)d_in[4];
    const float* mw  = (const float*)d_in[5];

    const int B = in_sizes[1];
    const int T = in_sizes[0] / B;

    dim3 block(32 * WARPS_PER_ROW);
    dim3 grid(B);
    bbm_kernel<<<grid, block>>>(obs, a1, b1, a2, b2, mw, (float*)d_out, B, T);
}

// round 6
// speedup vs baseline: 2.3400x; 1.6558x over previous
#include <cuda_runtime.h>

#define FULLMASK 0xFFFFFFFFu
#define WARPS_PER_ROW 8

// One 256-thread block per row; each warp owns a 1024-element chunk.
// R3 skeleton (sequential sub-iterations, small state) with:
//  - all ballots/lane-prefixes hoisted to an integer-only pre-pass (s0pack)
//  - streaming cache hints: __ldcs on obs, __stcs on all 5 output planes
//  - launch_bounds(256,5): guard at 51 regs (R3 natural = 47; no squeeze)
__global__ void __launch_bounds__(32 * WARPS_PER_ROW, 5)
bbm_kernel(const float* __restrict__ obs,
           const float* __restrict__ alpha1,
           const float* __restrict__ beta1,
           const float* __restrict__ alpha2,
           const float* __restrict__ beta2,
           const float* __restrict__ mixw,
           float* __restrict__ out,
           int B, int T)
{
    const int wid  = threadIdx.x >> 5;
    const int lane = threadIdx.x & 31;
    const int row  = blockIdx.x;

    const unsigned ltmask = (lane == 0) ? 0u : (FULLMASK >> (32 - lane));

    const float a1c = __ldg(alpha1 + row);
    const float b1c = __ldg(beta1  + row);
    const float a2c = __ldg(alpha2 + row);
    const float b2c = __ldg(beta2  + row);
    const float ab1 = a1c + b1c;
    const float ab2 = a2c + b2c;
    const float w   = __ldg(mixw);
    const float omw = 1.0f - w;

    const int chunk = T / WARPS_PER_ROW;   // 1024

    const float4* __restrict__ orow =
        reinterpret_cast<const float4*>(obs + (size_t)row * (size_t)T);

    const size_t NT = (size_t)B * (size_t)T;
    float* o_a1 = out + (size_t)row * (size_t)T;

    __shared__ int smem_cnt[WARPS_PER_ROW];

    // ---------- Phase 1: streaming load of chunk, pack bits, count ----------
    unsigned packed = 0;
    const int vbase = wid * (chunk >> 2) + lane;
    #pragma unroll
    for (int i = 0; i < 8; ++i) {
        const float4 v = __ldcs(orow + vbase + i * 32);
        unsigned nib = (unsigned)(v.x > 0.5f)
                     | ((unsigned)(v.y > 0.5f) << 1)
                     | ((unsigned)(v.z > 0.5f) << 2)
                     | ((unsigned)(v.w > 0.5f) << 3);
        packed |= nib << (4 * i);
    }
    const int warpcnt = __reduce_add_sync(FULLMASK, __popc(packed));
    if (lane == 0) smem_cnt[wid] = warpcnt;
    __syncthreads();

    int s_start = 0;
    #pragma unroll
    for (int k = 0; k < WARPS_PER_ROW; ++k)
        if (k < wid) s_start += smem_cnt[k];

    // ---------- chunk D_base via lgamma closed form ----------
    float D_carry = 0.0f;
    if (wid != 0) {
        const float tf = (float)(wid * chunk);
        const float sf = (float)s_start;
        const float ff = tf - sf;
        const float d2 = (lgammaf(a2c + sf) + lgammaf(b2c + ff) - lgammaf(ab2 + tf))
                       - (lgammaf(a2c) + lgammaf(b2c) - lgammaf(ab2));
        const float d1 = (lgammaf(a1c + sf) + lgammaf(b1c + ff) - lgammaf(ab1 + tf))
                       - (lgammaf(a1c) + lgammaf(b1c) - lgammaf(ab1));
        D_carry = d2 - d1;
    }

    // ---------- integer pre-pass: per-sub-iter per-lane s0, packed 16-bit ----------
    unsigned s0pack[4];
    {
        int s_run = s_start;
        #pragma unroll
        for (int i = 0; i < 8; ++i) {
            const unsigned nib = (packed >> (4 * i)) & 0xF;
            const unsigned m0 = __ballot_sync(FULLMASK, nib & 1u);
            const unsigned m1 = __ballot_sync(FULLMASK, nib & 2u);
            const unsigned m2 = __ballot_sync(FULLMASK, nib & 4u);
            const unsigned m3 = __ballot_sync(FULLMASK, nib & 8u);
            const int lp = __popc(m0 & ltmask) + __popc(m1 & ltmask)
                         + __popc(m2 & ltmask) + __popc(m3 & ltmask);
            const unsigned s0 = (unsigned)(s_run + lp);
            if (i & 1) s0pack[i >> 1] |= s0 << 16;
            else       s0pack[i >> 1]  = s0;
            s_run += __popc(m0) + __popc(m1) + __popc(m2) + __popc(m3);
        }
    }

    const int tchunk = wid * chunk;

    // ---------- Phase 2: sequential sub-iterations (small live state) ----------
    #pragma unroll
    for (int it = 0; it < 8; ++it) {
        const int s0 = (int)((s0pack[it >> 1] >> ((it & 1) * 16)) & 0xFFFFu);
        const unsigned nib = (packed >> (4 * it)) & 0xF;
        const int b0 = (nib)      & 1;
        const int b1 = (nib >> 1) & 1;
        const int b2 = (nib >> 2) & 1;
        const int b3 = (nib >> 3) & 1;

        const int   t0  = tchunk + (it << 7) + (lane << 2);
        const float t0f = (float)t0;

        // per-element ratio factors; exclusive cumulative products
        int bj[4] = {b0, b1, b2, b3};
        float sfv[4], num[4], den[4];
        int ss = s0;
        #pragma unroll
        for (int j = 0; j < 4; ++j) {
            const float tf = t0f + (float)j;
            const float sf = (float)ss;
            const float ff = tf - sf;
            sfv[j] = sf;
            const float xv = bj[j] ? sf  : ff;
            const float c2 = bj[j] ? a2c : b2c;
            const float c1 = bj[j] ? a1c : b1c;
            num[j] = (c2 + xv) * (ab1 + tf);
            den[j] = (c1 + xv) * (ab2 + tf);
            ss += bj[j];
        }
        float cnex[4], cdex[4];
        cnex[0] = 1.0f;             cdex[0] = 1.0f;
        cnex[1] = num[0];           cdex[1] = den[0];
        cnex[2] = cnex[1] * num[1]; cdex[2] = cdex[1] * den[1];
        cnex[3] = cnex[2] * num[2]; cdex[3] = cdex[2] * den[2];
        const float cnInc = cnex[3] * num[3];
        const float cdInc = cdex[3] * den[3];

        const float dacc = __logf(__fdividef(cnInc, cdInc));

        float finc = dacc;
        #pragma unroll
        for (int d = 1; d < 32; d <<= 1) {
            float n = __shfl_up_sync(FULLMASK, finc, d);
            if (lane >= d) finc += n;
        }
        const float Dbase = D_carry + (finc - dacc);
        const float Dtot  = __shfl_sync(FULLMASK, finc, 31);

        const float omwEb = omw * __expf(Dbase);

        float oa1[4], ob1[4], oa2[4], ob2[4], opm[4];
        #pragma unroll
        for (int j = 0; j < 4; ++j) {
            const float tf = t0f + (float)j;
            const float sf = sfv[j];
            const float ff = tf - sf;
            oa1[j] = a1c + sf;
            ob1[j] = b1c + ff;
            oa2[j] = a2c + sf;
            ob2[j] = b2c + ff;
            const float wn = w * cdex[j];
            opm[j] = __fdividef(wn, fmaf(omwEb, cnex[j], wn));
        }

        float* p = o_a1 + t0;
        __stcs(reinterpret_cast<float4*>(p),          make_float4(oa1[0], oa1[1], oa1[2], oa1[3]));
        __stcs(reinterpret_cast<float4*>(p + NT),     make_float4(ob1[0], ob1[1], ob1[2], ob1[3]));
        __stcs(reinterpret_cast<float4*>(p + 2 * NT), make_float4(oa2[0], oa2[1], oa2[2], oa2[3]));
        __stcs(reinterpret_cast<float4*>(p + 3 * NT), make_float4(ob2[0], ob2[1], ob2[2], ob2[3]));
        __stcs(reinterpret_cast<float4*>(p + 4 * NT), make_float4(opm[0], opm[1], opm[2], opm[3]));

        D_carry += Dtot;
    }
}

extern "C" void kernel_launch(void* const* d_in, const int* in_sizes, int n_in,
                              void* d_out, int out_size)
{
    const float* obs = (const float*)d_in[0];
    const float* a1  = (const float*)d_in[1];
    const float* b1  = (const float*)d_in[2];
    const float* a2  = (const float*)d_in[3];
    const float* b2  = (const float*)d_in[4];
    const float* mw  = (const float*)d_in[5];

    const int B = in_sizes[1];
    const int T = in_sizes[0] / B;

    dim3 block(32 * WARPS_PER_ROW);
    dim3 grid(B);
    bbm_kernel<<<grid, block>>>(obs, a1, b1, a2, b2, mw, (float*)d_out, B, T);
}